// round 3
// baseline (speedup 1.0000x reference)
#include <cuda_runtime.h>

#define BB 2
#define CC 64
#define HH 128
#define WW 128
#define NN 4096
#define NS 8   // B * GRID^2 slices

// ---------------- device scratch (no allocations allowed) ----------------
__device__ float g_q[NS][CC][NN];
__device__ float g_k[NS][CC][NN];
__device__ float g_a[NS][CC][NN];   // gets scaled in-place by 1/Z[j]
__device__ float g_b[NS][CC][NN];
__device__ float g_Z[NS][NN];
__device__ float g_rZ[NS][NN];
__device__ float g_o[NS][CC][NN];
__device__ float g_E[(size_t)NS * NN * NN];   // 536 MB exp(S) scratch

// ---------------- zero Z (graph replays must start clean) ----------------
__global__ void zeroZ_kernel() {
    int i = blockIdx.x * blockDim.x + threadIdx.x;
    if (i < NS * NN) (&g_Z[0][0])[i] = 0.0f;
}

// ---------------- 4 fused 1x1 convs + regionize ----------------
// block: (wtile in {0,1}, h in 0..127, b in {0,1}); 256 threads
// threads 0-63 -> q, 64-127 -> k, 128-191 -> a, 192-255 -> b
__global__ void conv4_kernel(const float* __restrict__ x,
                             const float* __restrict__ Wq, const float* __restrict__ bq,
                             const float* __restrict__ Wk, const float* __restrict__ bk,
                             const float* __restrict__ Wa, const float* __restrict__ ba,
                             const float* __restrict__ Wb, const float* __restrict__ bb) {
    __shared__ float xs[CC][64];
    int wt = blockIdx.x, h = blockIdx.y, b = blockIdx.z;
    int tid = threadIdx.x;
    for (int idx = tid; idx < CC * 64; idx += 256) {
        int c = idx >> 6, p = idx & 63;
        xs[c][p] = x[(((size_t)b * CC + c) * HH + h) * WW + wt * 64 + p];
    }
    __syncthreads();
    int p = tid & 63;
    int grp = tid >> 6;
    const float* Wm = (grp == 0) ? Wq : (grp == 1) ? Wk : (grp == 2) ? Wa : Wb;
    const float* bv = (grp == 0) ? bq : (grp == 1) ? bk : (grp == 2) ? ba : bb;
    int s = b * 4 + (h >> 6) * 2 + wt;
    int n = (h & 63) * 64 + p;
    float* outp = (grp == 0) ? &g_q[s][0][0] : (grp == 1) ? &g_k[s][0][0]
                : (grp == 2) ? &g_a[s][0][0] : &g_b[s][0][0];
    #pragma unroll 1
    for (int oc = 0; oc < CC; oc++) {
        float acc = bv[oc];
        const float4* wr = (const float4*)(Wm + oc * CC);
        #pragma unroll
        for (int c4 = 0; c4 < 16; c4++) {
            float4 w = wr[c4];
            acc += w.x * xs[c4 * 4 + 0][p] + w.y * xs[c4 * 4 + 1][p]
                 + w.z * xs[c4 * 4 + 2][p] + w.w * xs[c4 * 4 + 3][p];
        }
        outp[oc * NN + n] = acc;
    }
}

// ---------------- E = exp(q^T k / 8), Z[n] += row sums ----------------
// grid: (m-tile 64, n-tile 64, slice 8); block 256 (16x16), 4x4 microtile
__global__ void ez_kernel() {
    __shared__ float qs[CC][68];
    __shared__ float ks[CC][68];
    int s = blockIdx.z;
    int n0 = blockIdx.y * 64, m0 = blockIdx.x * 64;
    int tid = threadIdx.x;
    {
        int cbase = tid >> 4;
        int i = (tid & 15) * 4;
        #pragma unroll
        for (int r = 0; r < 4; r++) {
            int c = r * 16 + cbase;
            *(float4*)&qs[c][i] = *(const float4*)&g_q[s][c][n0 + i];
            *(float4*)&ks[c][i] = *(const float4*)&g_k[s][c][m0 + i];
        }
    }
    __syncthreads();
    int tx = tid & 15, ty = tid >> 4;
    float acc[4][4] = {};
    #pragma unroll 8
    for (int c = 0; c < CC; c++) {
        float4 q4 = *(const float4*)&qs[c][ty * 4];
        float4 k4 = *(const float4*)&ks[c][tx * 4];
        acc[0][0] += q4.x * k4.x; acc[0][1] += q4.x * k4.y; acc[0][2] += q4.x * k4.z; acc[0][3] += q4.x * k4.w;
        acc[1][0] += q4.y * k4.x; acc[1][1] += q4.y * k4.y; acc[1][2] += q4.y * k4.z; acc[1][3] += q4.y * k4.w;
        acc[2][0] += q4.z * k4.x; acc[2][1] += q4.z * k4.y; acc[2][2] += q4.z * k4.z; acc[2][3] += q4.z * k4.w;
        acc[3][0] += q4.w * k4.x; acc[3][1] += q4.w * k4.y; acc[3][2] += q4.w * k4.z; acc[3][3] += q4.w * k4.w;
    }
    #pragma unroll
    for (int u = 0; u < 4; u++) {
        float4 ev;
        ev.x = __expf(acc[u][0] * 0.125f);
        ev.y = __expf(acc[u][1] * 0.125f);
        ev.z = __expf(acc[u][2] * 0.125f);
        ev.w = __expf(acc[u][3] * 0.125f);
        int n = n0 + ty * 4 + u;
        *(float4*)&g_E[((size_t)s * NN + n) * NN + m0 + tx * 4] = ev;
        float rs = ev.x + ev.y + ev.z + ev.w;
        rs += __shfl_xor_sync(0xffffffffu, rs, 8, 16);
        rs += __shfl_xor_sync(0xffffffffu, rs, 4, 16);
        rs += __shfl_xor_sync(0xffffffffu, rs, 2, 16);
        rs += __shfl_xor_sync(0xffffffffu, rs, 1, 16);
        if (tx == 0) atomicAdd(&g_Z[s][n], rs);
    }
}

// ---------------- a *= 1/Z[j] (folds row-softmax norm of term 1); rZ ----------------
__global__ void scale_a_kernel() {
    int n = blockIdx.x * 256 + threadIdx.x;
    int c = blockIdx.y;
    int s = blockIdx.z;
    float rz = 1.0f / g_Z[s][n];
    g_a[s][c][n] *= rz;
    if (c == 0) g_rZ[s][n] = rz;
}

// ---------------- out = a' @ E + diag(1/Z) applied to b @ E^T ----------------
// grid: (m-tile 64, slice 8); block 256 (16x16); each thread 4c x 4m for both terms
__global__ void outk_kernel() {
    extern __shared__ float sm[];
    float* As  = sm;                 // [64][68]  a' (c, j)
    float* Bs  = sm + 64 * 68;       // [64][68]  b  (c, j)
    float* E1s = sm + 2 * 64 * 68;   // [64][68]  E[j][m]
    float* E2t = sm + 3 * 64 * 68;   // [64][68]  E[m][j] transposed -> [j][m]
    int s = blockIdx.y;
    int m0 = blockIdx.x * 64;
    int tid = threadIdx.x;
    int tx = tid & 15, ty = tid >> 4;
    int lc = tid >> 2;   // 0..63
    int lq = tid & 3;    // 0..3
    float o1[4][4] = {};
    float o2[4][4] = {};

    #pragma unroll 1
    for (int j0 = 0; j0 < NN; j0 += 64) {
        __syncthreads();
        #pragma unroll
        for (int f = 0; f < 4; f++) {
            int jj = lq * 4 + f * 16;
            *(float4*)&As[lc * 68 + jj]  = *(const float4*)&g_a[s][lc][j0 + jj];
            *(float4*)&Bs[lc * 68 + jj]  = *(const float4*)&g_b[s][lc][j0 + jj];
            // E1: rows j (=lc), cols m (=jj)
            *(float4*)&E1s[lc * 68 + jj] =
                *(const float4*)&g_E[((size_t)s * NN + j0 + lc) * NN + m0 + jj];
            // E2: rows m (=lc), cols j (=jj..jj+3), transpose-store as [j][m]
            float4 ve2 = *(const float4*)&g_E[((size_t)s * NN + m0 + lc) * NN + j0 + jj];
            E2t[(jj + 0) * 68 + lc] = ve2.x;
            E2t[(jj + 1) * 68 + lc] = ve2.y;
            E2t[(jj + 2) * 68 + lc] = ve2.z;
            E2t[(jj + 3) * 68 + lc] = ve2.w;
        }
        __syncthreads();
        #pragma unroll 4
        for (int j4 = 0; j4 < 16; j4++) {
            float4 e1[4], e2[4];
            #pragma unroll
            for (int d = 0; d < 4; d++) {
                e1[d] = *(const float4*)&E1s[(4 * j4 + d) * 68 + tx * 4];
                e2[d] = *(const float4*)&E2t[(4 * j4 + d) * 68 + tx * 4];
            }
            #pragma unroll
            for (int u = 0; u < 4; u++) {
                float4 av = *(const float4*)&As[(ty * 4 + u) * 68 + 4 * j4];
                float4 bv = *(const float4*)&Bs[(ty * 4 + u) * 68 + 4 * j4];
                o1[u][0] += av.x * e1[0].x + av.y * e1[1].x + av.z * e1[2].x + av.w * e1[3].x;
                o1[u][1] += av.x * e1[0].y + av.y * e1[1].y + av.z * e1[2].y + av.w * e1[3].y;
                o1[u][2] += av.x * e1[0].z + av.y * e1[1].z + av.z * e1[2].z + av.w * e1[3].z;
                o1[u][3] += av.x * e1[0].w + av.y * e1[1].w + av.z * e1[2].w + av.w * e1[3].w;
                o2[u][0] += bv.x * e2[0].x + bv.y * e2[1].x + bv.z * e2[2].x + bv.w * e2[3].x;
                o2[u][1] += bv.x * e2[0].y + bv.y * e2[1].y + bv.z * e2[2].y + bv.w * e2[3].y;
                o2[u][2] += bv.x * e2[0].z + bv.y * e2[1].z + bv.z * e2[2].z + bv.w * e2[3].z;
                o2[u][3] += bv.x * e2[0].w + bv.y * e2[1].w + bv.z * e2[2].w + bv.w * e2[3].w;
            }
        }
    }
    float4 rz = *(const float4*)&g_rZ[s][m0 + tx * 4];
    #pragma unroll
    for (int u = 0; u < 4; u++) {
        float4 res;
        res.x = o1[u][0] + o2[u][0] * rz.x;
        res.y = o1[u][1] + o2[u][1] * rz.y;
        res.z = o1[u][2] + o2[u][2] * rz.z;
        res.w = o1[u][3] + o2[u][3] * rz.w;
        *(float4*)&g_o[s][ty * 4 + u][m0 + tx * 4] = res;
    }
}

// ---------------- final 1x1 conv + un-regionize ----------------
__global__ void finalconv_kernel(const float* __restrict__ Wo, const float* __restrict__ bo,
                                 float* __restrict__ out) {
    __shared__ float os[CC][64];
    int wt = blockIdx.x, h = blockIdx.y, b = blockIdx.z;
    int tid = threadIdx.x;
    int s = b * 4 + (h >> 6) * 2 + wt;
    int nbase = (h & 63) * 64;
    for (int idx = tid; idx < CC * 64; idx += 256) {
        int c = idx >> 6, p = idx & 63;
        os[c][p] = g_o[s][c][nbase + p];
    }
    __syncthreads();
    int p = tid & 63, grp = tid >> 6;
    #pragma unroll 1
    for (int i = 0; i < 16; i++) {
        int oc = grp * 16 + i;
        float acc = bo[oc];
        const float4* wr = (const float4*)(Wo + oc * CC);
        #pragma unroll
        for (int c4 = 0; c4 < 16; c4++) {
            float4 w = wr[c4];
            acc += w.x * os[c4 * 4 + 0][p] + w.y * os[c4 * 4 + 1][p]
                 + w.z * os[c4 * 4 + 2][p] + w.w * os[c4 * 4 + 3][p];
        }
        out[(((size_t)b * CC + oc) * HH + h) * WW + wt * 64 + p] = acc;
    }
}

// ---------------- launch ----------------
extern "C" void kernel_launch(void* const* d_in, const int* in_sizes, int n_in,
                              void* d_out, int out_size) {
    const float* x  = (const float*)d_in[0];
    const float* Wq = (const float*)d_in[1];
    const float* bq = (const float*)d_in[2];
    const float* Wk = (const float*)d_in[3];
    const float* bk = (const float*)d_in[4];
    const float* Wa = (const float*)d_in[5];
    const float* ba = (const float*)d_in[6];
    const float* Wb = (const float*)d_in[7];
    const float* bb = (const float*)d_in[8];
    const float* Wo = (const float*)d_in[9];
    const float* bo = (const float*)d_in[10];
    float* out = (float*)d_out;

    const int outk_smem = 4 * 64 * 68 * (int)sizeof(float);   // 69632 B
    cudaFuncSetAttribute(outk_kernel, cudaFuncAttributeMaxDynamicSharedMemorySize, outk_smem);

    zeroZ_kernel<<<(NS * NN + 255) / 256, 256>>>();
    conv4_kernel<<<dim3(2, HH, BB), 256>>>(x, Wq, bq, Wk, bk, Wa, ba, Wb, bb);
    ez_kernel<<<dim3(64, 64, NS), 256>>>();
    scale_a_kernel<<<dim3(NN / 256, CC, NS), 256>>>();
    outk_kernel<<<dim3(64, NS), 256, outk_smem>>>();
    finalconv_kernel<<<dim3(2, HH, BB), 256>>>(Wo, bo, out);
}

// round 7
// speedup vs baseline: 3.3906x; 3.3906x over previous
#include <cuda_runtime.h>
#include <cuda_bf16.h>
#include <cstdint>

#define CC 64
#define HH 128
#define WW 128
#define NN 4096
#define NS 8
#define BB 2

__device__ float g_a[NS][CC][NN];
__device__ float g_b[NS][CC][NN];
__device__ float g_Z[NS][NN];
__device__ float g_rZ[NS][NN];
__device__ float g_o[NS][CC][NN];
__device__ __nv_bfloat16 g_qh[NS][NN][CC], g_ql[NS][NN][CC];
__device__ __nv_bfloat16 g_kh[NS][NN][CC], g_kl[NS][NN][CC];
__device__ __nv_bfloat16 g_as[NS][2 * CC][NN], g_bs[NS][2 * CC][NN];
__device__ __nv_bfloat16 g_Eh[(size_t)NS * NN * NN], g_El[(size_t)NS * NN * NN];

__device__ __forceinline__ uint32_t s2u(const void* p) {
    uint32_t a;
    asm("{ .reg .u64 t; cvta.to.shared.u64 t, %1; cvt.u32.u64 %0, t; }" : "=r"(a) : "l"(p));
    return a;
}
__device__ __forceinline__ void ldsm4(uint32_t* r, uint32_t a) {
    asm volatile("ldmatrix.sync.aligned.m8n8.x4.shared.b16 {%0,%1,%2,%3}, [%4];"
        : "=r"(r[0]), "=r"(r[1]), "=r"(r[2]), "=r"(r[3]) : "r"(a));
}
__device__ __forceinline__ void ldsm4t(uint32_t* r, uint32_t a) {
    asm volatile("ldmatrix.sync.aligned.m8n8.x4.trans.shared.b16 {%0,%1,%2,%3}, [%4];"
        : "=r"(r[0]), "=r"(r[1]), "=r"(r[2]), "=r"(r[3]) : "r"(a));
}
__device__ __forceinline__ void mma16816(float* d, const uint32_t* a, const uint32_t* b) {
    asm volatile("mma.sync.aligned.m16n8k16.row.col.f32.bf16.bf16.f32 "
        "{%0,%1,%2,%3}, {%4,%5,%6,%7}, {%8,%9}, {%0,%1,%2,%3};"
        : "+f"(d[0]), "+f"(d[1]), "+f"(d[2]), "+f"(d[3])
        : "r"(a[0]), "r"(a[1]), "r"(a[2]), "r"(a[3]), "r"(b[0]), "r"(b[1]));
}
__device__ __forceinline__ uint32_t pk(float a, float b) {
    __nv_bfloat162 t(__float2bfloat16(a), __float2bfloat16(b));
    return *reinterpret_cast<uint32_t*>(&t);
}

__global__ void zeroZ_kernel() {
    int i = blockIdx.x * 256 + threadIdx.x;
    if (i < NS * NN) (&g_Z[0][0])[i] = 0.0f;
}

// -------- conv: q,k -> split bf16 [n][c]; a,b -> fp32 [c][n] --------
__global__ void conv4_kernel(const float* __restrict__ x,
                             const float* __restrict__ Wq, const float* __restrict__ bq,
                             const float* __restrict__ Wk, const float* __restrict__ bk,
                             const float* __restrict__ Wa, const float* __restrict__ ba,
                             const float* __restrict__ Wb, const float* __restrict__ bb) {
    __shared__ float xs[CC][64];
    int wt = blockIdx.x, h = blockIdx.y, b = blockIdx.z, tid = threadIdx.x;
    for (int i = tid; i < CC * 64; i += 256)
        xs[i >> 6][i & 63] = x[(((size_t)b * CC + (i >> 6)) * HH + h) * WW + wt * 64 + (i & 63)];
    __syncthreads();
    int p = tid & 63, grp = tid >> 6;
    int s = b * 4 + (h >> 6) * 2 + wt;
    int n = (h & 63) * 64 + p;
    const float* Wm = (grp == 0) ? Wq : (grp == 1) ? Wk : (grp == 2) ? Wa : Wb;
    const float* bv = (grp == 0) ? bq : (grp == 1) ? bk : (grp == 2) ? ba : bb;
    if (grp < 2) {
        float av[CC];
        #pragma unroll 1
        for (int oc = 0; oc < CC; oc++) {
            float acc = bv[oc];
            const float4* wr = (const float4*)(Wm + oc * CC);
            #pragma unroll
            for (int c4 = 0; c4 < 16; c4++) {
                float4 w = wr[c4];
                acc += w.x * xs[c4 * 4][p] + w.y * xs[c4 * 4 + 1][p] + w.z * xs[c4 * 4 + 2][p] + w.w * xs[c4 * 4 + 3][p];
            }
            av[oc] = acc;
        }
        uint32_t* ph = (uint32_t*)((grp == 0) ? &g_qh[s][n][0] : &g_kh[s][n][0]);
        uint32_t* pl = (uint32_t*)((grp == 0) ? &g_ql[s][n][0] : &g_kl[s][n][0]);
        #pragma unroll
        for (int c2 = 0; c2 < 32; c2++) {
            float v0 = av[2 * c2], v1 = av[2 * c2 + 1];
            float h0 = __bfloat162float(__float2bfloat16(v0));
            float h1 = __bfloat162float(__float2bfloat16(v1));
            ph[c2] = pk(v0, v1);
            pl[c2] = pk(v0 - h0, v1 - h1);
        }
    } else {
        float* outp = (grp == 2) ? &g_a[s][0][0] : &g_b[s][0][0];
        #pragma unroll 1
        for (int oc = 0; oc < CC; oc++) {
            float acc = bv[oc];
            const float4* wr = (const float4*)(Wm + oc * CC);
            #pragma unroll
            for (int c4 = 0; c4 < 16; c4++) {
                float4 w = wr[c4];
                acc += w.x * xs[c4 * 4][p] + w.y * xs[c4 * 4 + 1][p] + w.z * xs[c4 * 4 + 2][p] + w.w * xs[c4 * 4 + 3][p];
            }
            outp[oc * NN + n] = acc;
        }
    }
}

// -------- ez: E = exp(q^T k / 8) via mma.sync, split store, Z rowsums --------
// block = 128n x 128m; 8 warps, warp tile 32n x 64m
__global__ void __launch_bounds__(256, 2) ez_kernel() {
    extern __shared__ char sm[];
    uint32_t sb = s2u(sm);
    int s = blockIdx.z, n0 = blockIdx.y * 128, m0 = blockIdx.x * 128;
    int tid = threadIdx.x, w = tid >> 5, ln = tid & 31;
    // planes: qh@0 ql@18432 kh@36864 kl@55296, rows padded to 72 bf16 (144B)
    const __nv_bfloat16* srcs[4] = {&g_qh[s][n0][0], &g_ql[s][n0][0], &g_kh[s][m0][0], &g_kl[s][m0][0]};
    #pragma unroll
    for (int pl = 0; pl < 4; pl++) {
        const uint4* sp = (const uint4*)srcs[pl];
        char* dp = sm + pl * 18432;
        for (int u = tid; u < 1024; u += 256)
            *(uint4*)(dp + (u >> 3) * 144 + (u & 7) * 16) = sp[u];
    }
    __syncthreads();
    int n_off = (w >> 1) * 32, m_off = (w & 1) * 64;
    int g = ln >> 2, tg = ln & 3;
    float acc[2][8][4];
    #pragma unroll
    for (int i = 0; i < 2; i++)
        #pragma unroll
        for (int j = 0; j < 8; j++)
            #pragma unroll
            for (int q = 0; q < 4; q++) acc[i][j][q] = 0.f;
    #pragma unroll 1
    for (int pass = 0; pass < 3; pass++) {  // qh*kh, qh*kl, ql*kh
        uint32_t qb = sb + ((pass == 2) ? 18432u : 0u);
        uint32_t kb = sb + 36864u + ((pass == 1) ? 18432u : 0u);
        #pragma unroll
        for (int k16 = 0; k16 < 4; k16++) {
            int cb = k16 * 16;
            uint32_t aF[2][4];
            #pragma unroll
            for (int mf = 0; mf < 2; mf++)
                ldsm4(aF[mf], qb + (n_off + mf * 16 + (ln & 15)) * 144 + (cb + (ln >> 4) * 8) * 2);
            #pragma unroll
            for (int np = 0; np < 4; np++) {
                uint32_t bF[4];
                ldsm4(bF, kb + (m_off + np * 16 + (ln & 7) + ((ln >> 4) << 3)) * 144 + (cb + ((ln >> 3) & 1) * 8) * 2);
                mma16816(acc[0][2 * np], aF[0], bF);
                mma16816(acc[0][2 * np + 1], aF[0], bF + 2);
                mma16816(acc[1][2 * np], aF[1], bF);
                mma16816(acc[1][2 * np + 1], aF[1], bF + 2);
            }
        }
    }
    // exp + row sums
    #pragma unroll
    for (int mf = 0; mf < 2; mf++) {
        float r0 = 0.f, r1 = 0.f;
        #pragma unroll
        for (int nf = 0; nf < 8; nf++) {
            #pragma unroll
            for (int q = 0; q < 4; q++) acc[mf][nf][q] = __expf(acc[mf][nf][q] * 0.125f);
            r0 += acc[mf][nf][0] + acc[mf][nf][1];
            r1 += acc[mf][nf][2] + acc[mf][nf][3];
        }
        r0 += __shfl_xor_sync(~0u, r0, 1); r0 += __shfl_xor_sync(~0u, r0, 2);
        r1 += __shfl_xor_sync(~0u, r1, 1); r1 += __shfl_xor_sync(~0u, r1, 2);
        if (tg == 0) {
            atomicAdd(&g_Z[s][n0 + n_off + mf * 16 + g], r0);
            atomicAdd(&g_Z[s][n0 + n_off + mf * 16 + g + 8], r1);
        }
    }
    __syncthreads();
    // stage hi@0, lo@36864 as [128][136] bf16 (272B rows) for coalesced store
    #pragma unroll
    for (int mf = 0; mf < 2; mf++)
        #pragma unroll
        for (int nf = 0; nf < 8; nf++) {
            int col = m_off + nf * 8 + 2 * tg;
            int r0w = n_off + mf * 16 + g, r1w = r0w + 8;
            float v0 = acc[mf][nf][0], v1 = acc[mf][nf][1], v2 = acc[mf][nf][2], v3 = acc[mf][nf][3];
            float h0 = __bfloat162float(__float2bfloat16(v0));
            float h1 = __bfloat162float(__float2bfloat16(v1));
            float h2 = __bfloat162float(__float2bfloat16(v2));
            float h3 = __bfloat162float(__float2bfloat16(v3));
            *(uint32_t*)(sm + r0w * 272 + col * 2) = pk(v0, v1);
            *(uint32_t*)(sm + 36864 + r0w * 272 + col * 2) = pk(v0 - h0, v1 - h1);
            *(uint32_t*)(sm + r1w * 272 + col * 2) = pk(v2, v3);
            *(uint32_t*)(sm + 36864 + r1w * 272 + col * 2) = pk(v2 - h2, v3 - h3);
        }
    __syncthreads();
    for (int u = tid; u < 2048; u += 256) {
        int row = u >> 4, ch = u & 15;
        size_t base = ((size_t)s * NN + n0 + row) * NN + m0 + ch * 8;
        *(uint4*)&g_Eh[base] = *(uint4*)(sm + row * 272 + ch * 16);
        *(uint4*)&g_El[base] = *(uint4*)(sm + 36864 + row * 272 + ch * 16);
    }
}

// -------- scale a by 1/Z, split a,b into stacked hi/lo bf16 --------
__global__ void scale_split_kernel() {
    int n = blockIdx.x * 256 + threadIdx.x, c = blockIdx.y, s = blockIdx.z;
    float rz = 1.0f / g_Z[s][n];
    if (c == 0) g_rZ[s][n] = rz;
    float av = g_a[s][c][n] * rz, bv = g_b[s][c][n];
    float ah = __bfloat162float(__float2bfloat16(av));
    float bh = __bfloat162float(__float2bfloat16(bv));
    g_as[s][c][n] = __float2bfloat16(av);
    g_as[s][c + CC][n] = __float2bfloat16(av - ah);
    g_bs[s][c][n] = __float2bfloat16(bv);
    g_bs[s][c + CC][n] = __float2bfloat16(bv - bh);
}

// -------- outk: out = a'@E + diag(rZ)*(b @ E-rows) via mma.sync --------
// block = 64c x 128m, 8 warps, warp tile 16c x 64m; j swept in chunks of 64
__global__ void __launch_bounds__(256, 2) outk_kernel() {
    extern __shared__ char sm[];
    uint32_t sb = s2u(sm);
    int s = blockIdx.y, m0 = blockIdx.x * 128;
    int tid = threadIdx.x, w = tid >> 5, ln = tid & 31;
    const uint32_t AH = 0, AL = 9216, BH = 18432, BL = 27648;
    const uint32_t E1H = 36864, E1L = 54272, E2H = 71680, E2L = 90112;
    int c_off = (w >> 1) * 16, mw = (w & 1) * 64;
    int g = ln >> 2, tg = ln & 3;
    float ac1[8][4], ac2[8][4];
    #pragma unroll
    for (int i = 0; i < 8; i++)
        #pragma unroll
        for (int q = 0; q < 4; q++) { ac1[i][q] = 0.f; ac2[i][q] = 0.f; }

    #pragma unroll 1
    for (int it = 0; it < 64; it++) {
        int j0 = it * 64;
        __syncthreads();
        // A planes [64c][64j] x4 (ah,al,bh,bl), 144B rows
        for (int u = tid; u < 2048; u += 256) {
            int pl = u >> 9, rem = u & 511, row = rem >> 3, ch = rem & 7;
            const __nv_bfloat16* src = (pl < 2) ? &g_as[s][row + (pl & 1) * 64][j0]
                                                : &g_bs[s][row + (pl & 1) * 64][j0];
            *(uint4*)(sm + pl * 9216 + row * 144 + ch * 16) = ((const uint4*)src)[ch];
        }
        // E1 [64j][128m] hi/lo, 272B rows (term1, consumed via ldmatrix.trans)
        for (int u = tid; u < 2048; u += 256) {
            int pl = u >> 10, rem = u & 1023, row = rem >> 4, ch = rem & 15;
            const __nv_bfloat16* src = pl ? &g_El[((size_t)s * NN + j0 + row) * NN + m0]
                                          : &g_Eh[((size_t)s * NN + j0 + row) * NN + m0];
            *(uint4*)(sm + E1H + pl * 17408 + row * 272 + ch * 16) = ((const uint4*)src)[ch];
        }
        // E2 [128m][64j] hi/lo, 144B rows (term2, K-major direct)
        for (int u = tid; u < 2048; u += 256) {
            int pl = u >> 10, rem = u & 1023, row = rem >> 3, ch = rem & 7;
            const __nv_bfloat16* src = pl ? &g_El[((size_t)s * NN + m0 + row) * NN + j0]
                                          : &g_Eh[((size_t)s * NN + m0 + row) * NN + j0];
            *(uint4*)(sm + E2H + pl * 18432 + row * 144 + ch * 16) = ((const uint4*)src)[ch];
        }
        __syncthreads();
        #pragma unroll
        for (int kb = 0; kb < 4; kb++) {
            int jb = kb * 16;
            uint32_t ah[4], al[4], bh[4], bl[4];
            uint32_t arow = (c_off + (ln & 15)) * 144 + (jb + (ln >> 4) * 8) * 2;
            ldsm4(ah, sb + AH + arow);
            ldsm4(al, sb + AL + arow);
            ldsm4(bh, sb + BH + arow);
            ldsm4(bl, sb + BL + arow);
            #pragma unroll
            for (int np = 0; np < 4; np++) {
                int mb = mw + np * 16;
                uint32_t e1h[4], e1l[4], e2h[4], e2l[4];
                uint32_t t1a = (jb + (ln & 15)) * 272 + (mb + (ln >> 4) * 8) * 2;
                ldsm4t(e1h, sb + E1H + t1a);
                ldsm4t(e1l, sb + E1L + t1a);
                uint32_t t2a = (mb + (ln & 7) + ((ln >> 4) << 3)) * 144 + (jb + ((ln >> 3) & 1) * 8) * 2;
                ldsm4(e2h, sb + E2H + t2a);
                ldsm4(e2l, sb + E2L + t2a);
                mma16816(ac1[2 * np], ah, e1h);     mma16816(ac1[2 * np + 1], ah, e1h + 2);
                mma16816(ac1[2 * np], al, e1h);     mma16816(ac1[2 * np + 1], al, e1h + 2);
                mma16816(ac1[2 * np], ah, e1l);     mma16816(ac1[2 * np + 1], ah, e1l + 2);
                mma16816(ac2[2 * np], bh, e2h);     mma16816(ac2[2 * np + 1], bh, e2h + 2);
                mma16816(ac2[2 * np], bl, e2h);     mma16816(ac2[2 * np + 1], bl, e2h + 2);
                mma16816(ac2[2 * np], bh, e2l);     mma16816(ac2[2 * np + 1], bh, e2l + 2);
            }
        }
    }
    #pragma unroll
    for (int nf = 0; nf < 8; nf++) {
        int m = m0 + mw + nf * 8 + 2 * tg;
        float rz0 = g_rZ[s][m], rz1 = g_rZ[s][m + 1];
        int c0 = c_off + g;
        g_o[s][c0][m]     = ac1[nf][0] + rz0 * ac2[nf][0];
        g_o[s][c0][m + 1] = ac1[nf][1] + rz1 * ac2[nf][1];
        g_o[s][c0 + 8][m]     = ac1[nf][2] + rz0 * ac2[nf][2];
        g_o[s][c0 + 8][m + 1] = ac1[nf][3] + rz1 * ac2[nf][3];
    }
}

// -------- final 1x1 conv + un-regionize --------
__global__ void finalconv_kernel(const float* __restrict__ Wo, const float* __restrict__ bo,
                                 float* __restrict__ out) {
    __shared__ float os[CC][64];
    int wt = blockIdx.x, h = blockIdx.y, b = blockIdx.z, tid = threadIdx.x;
    int s = b * 4 + (h >> 6) * 2 + wt;
    int nb = (h & 63) * 64;
    for (int i = tid; i < CC * 64; i += 256)
        os[i >> 6][i & 63] = g_o[s][i >> 6][nb + (i & 63)];
    __syncthreads();
    int p = tid & 63, grp = tid >> 6;
    #pragma unroll 1
    for (int i = 0; i < 16; i++) {
        int oc = grp * 16 + i;
        float acc = bo[oc];
        const float4* wr = (const float4*)(Wo + oc * CC);
        #pragma unroll
        for (int c4 = 0; c4 < 16; c4++) {
            float4 w = wr[c4];
            acc += w.x * os[c4 * 4][p] + w.y * os[c4 * 4 + 1][p] + w.z * os[c4 * 4 + 2][p] + w.w * os[c4 * 4 + 3][p];
        }
        out[(((size_t)b * CC + oc) * HH + h) * WW + wt * 64 + p] = acc;
    }
}

extern "C" void kernel_launch(void* const* d_in, const int* in_sizes, int n_in,
                              void* d_out, int out_size) {
    const float* x = (const float*)d_in[0];
    const float *Wq = (const float*)d_in[1], *bq = (const float*)d_in[2];
    const float *Wk = (const float*)d_in[3], *bk = (const float*)d_in[4];
    const float *Wa = (const float*)d_in[5], *ba = (const float*)d_in[6];
    const float *Wb = (const float*)d_in[7], *bb = (const float*)d_in[8];
    const float *Wo = (const float*)d_in[9], *bo = (const float*)d_in[10];
    float* out = (float*)d_out;

    const int EZ_SM = 73728;    // 4 x [128][72] bf16 operand planes
    const int OK_SM = 108544;   // A x4 + E1 x2 + E2 x2
    cudaFuncSetAttribute(ez_kernel, cudaFuncAttributeMaxDynamicSharedMemorySize, EZ_SM);
    cudaFuncSetAttribute(outk_kernel, cudaFuncAttributeMaxDynamicSharedMemorySize, OK_SM);

    zeroZ_kernel<<<(NS * NN + 255) / 256, 256>>>();
    conv4_kernel<<<dim3(2, HH, BB), 256>>>(x, Wq, bq, Wk, bk, Wa, ba, Wb, bb);
    ez_kernel<<<dim3(32, 32, NS), 256, EZ_SM>>>();
    scale_split_kernel<<<dim3(NN / 256, CC, NS), 256>>>();
    outk_kernel<<<dim3(32, NS), 256, OK_SM>>>();
    finalconv_kernel<<<dim3(2, HH, BB), 256>>>(Wo, bo, out);
}